// round 1
// baseline (speedup 1.0000x reference)
#include <cuda_runtime.h>
#include <cstdint>
#include <cstddef>

// ---------------------------------------------------------------------------
// RT-DETR v2 multiscale deformable attention, fp32 baseline.
//   B=32, Q=300, d=256, H=8, C=32, S=8400 (80x80+40x40+20x20), P=12 (3 lvls x 4)
// Stage 1: value = enc @ W_val + b_val, stored permuted to (B,H,S,C)
// Stage 2: per-query proj (offs+attn) + softmax + bilinear sampling -> mixed (B,Q,256)
// Stage 3: out = mixed @ W_out + b_out
// ---------------------------------------------------------------------------

#define B_SZ     32
#define Q_SZ     300
#define D_MODEL  256
#define H_SZ     8
#define C_SZ     32
#define S_SZ     8400
#define P_SZ     12
#define QG       5            // queries per block in sampling kernel

// scratch (module-scope device globals; no runtime allocation)
__device__ float g_value[(size_t)B_SZ * H_SZ * S_SZ * C_SZ];   // 275 MB
__device__ float g_mixed[(size_t)B_SZ * Q_SZ * D_MODEL];       // 9.8 MB

// ---------------------------------------------------------------------------
// fp32 SGEMM: C[M,N] = A[M,256] * B[256,N] + bias[N]
// 64x64 tile, BK=16, 256 threads, 4x4 per thread.
// PERM=true scatters the output to (B,H,S,C) layout (value projection).
// ---------------------------------------------------------------------------
template <bool PERM>
__global__ __launch_bounds__(256) void sgemm_k(
    const float* __restrict__ A, const float* __restrict__ B,
    const float* __restrict__ bias, float* __restrict__ C,
    int M, int N, int SROWS)
{
    __shared__ float As[16][68];
    __shared__ float Bs[16][68];

    const int tid = threadIdx.x;
    const int m0 = blockIdx.y * 64;
    const int n0 = blockIdx.x * 64;
    const int ty = tid >> 4, tx = tid & 15;

    const int arow = tid >> 2, akq = tid & 3;     // A loader: float4 per thread
    const int bkk  = tid >> 4, bnq = tid & 15;    // B loader: float4 per thread

    float acc[4][4] = {};

    for (int k0 = 0; k0 < 256; k0 += 16) {
        float4 av = *reinterpret_cast<const float4*>(
            &A[(size_t)(m0 + arow) * 256 + k0 + akq * 4]);
        As[akq * 4 + 0][arow] = av.x;
        As[akq * 4 + 1][arow] = av.y;
        As[akq * 4 + 2][arow] = av.z;
        As[akq * 4 + 3][arow] = av.w;

        float4 bv = *reinterpret_cast<const float4*>(
            &B[(size_t)(k0 + bkk) * N + n0 + bnq * 4]);
        *reinterpret_cast<float4*>(&Bs[bkk][bnq * 4]) = bv;

        __syncthreads();
        #pragma unroll
        for (int kk = 0; kk < 16; kk++) {
            float4 ra = *reinterpret_cast<const float4*>(&As[kk][ty * 4]);
            float4 rb = *reinterpret_cast<const float4*>(&Bs[kk][tx * 4]);
            float a_[4] = {ra.x, ra.y, ra.z, ra.w};
            float b_[4] = {rb.x, rb.y, rb.z, rb.w};
            #pragma unroll
            for (int i = 0; i < 4; i++)
                #pragma unroll
                for (int j = 0; j < 4; j++)
                    acc[i][j] += a_[i] * b_[j];
        }
        __syncthreads();
    }

    #pragma unroll
    for (int i = 0; i < 4; i++) {
        const int m = m0 + ty * 4 + i;
        int bb = 0, ss = 0;
        if (PERM) { bb = m / SROWS; ss = m % SROWS; }
        #pragma unroll
        for (int j = 0; j < 4; j++) {
            const int n = n0 + tx * 4 + j;
            const float v = acc[i][j] + bias[n];
            if (PERM) {
                const int h = n >> 5, c = n & 31;
                C[(((size_t)(bb * H_SZ + h)) * SROWS + ss) * C_SZ + c] = v;
            } else {
                C[(size_t)m * N + n] = v;
            }
        }
    }
}

// ---------------------------------------------------------------------------
// Fused: offset/attn projection + softmax + bilinear sampling.
// One block handles QG=5 queries of one batch. 256 threads.
// ---------------------------------------------------------------------------
__global__ __launch_bounds__(256) void deform_k(
    const float* __restrict__ hidden, const float* __restrict__ refp,
    const float* __restrict__ W_off, const float* __restrict__ b_off,
    const float* __restrict__ W_attn, const float* __restrict__ b_attn,
    const float* __restrict__ value, float* __restrict__ mixed)
{
    __shared__ float sh_h[QG][256];
    __shared__ float sh_proj[QG][288];   // [0,192): offsets, [192,288): attn

    const int tid = threadIdx.x;
    const int blk = blockIdx.x;                 // 0 .. B*(Q/QG)-1
    const int b   = blk / (Q_SZ / QG);
    const int q0  = (blk % (Q_SZ / QG)) * QG;

    #pragma unroll
    for (int g = 0; g < QG; g++)
        sh_h[g][tid] = hidden[((size_t)(b * Q_SZ + q0 + g)) * 256 + tid];
    __syncthreads();

    // --- projections: 288 columns, each thread handles 1-2 columns for all QG
    for (int j = tid; j < 288; j += 256) {
        const float* col;
        int ncols;
        float bia;
        if (j < 192) { col = W_off + j;         ncols = 192; bia = b_off[j]; }
        else         { col = W_attn + (j - 192); ncols = 96;  bia = b_attn[j - 192]; }
        float s[QG];
        #pragma unroll
        for (int g = 0; g < QG; g++) s[g] = 0.f;
        for (int k = 0; k < 256; k++) {
            const float w = col[(size_t)k * ncols];
            #pragma unroll
            for (int g = 0; g < QG; g++) s[g] += w * sh_h[g][k];
        }
        #pragma unroll
        for (int g = 0; g < QG; g++) sh_proj[g][j] = s[g] + bia;
    }
    __syncthreads();

    // --- softmax over 12 points per (g,h): QG*8 = 40 tasks
    if (tid < QG * H_SZ) {
        const int g = tid >> 3, h = tid & 7;
        float* L = &sh_proj[g][192 + h * P_SZ];
        float mx = L[0];
        #pragma unroll
        for (int p = 1; p < P_SZ; p++) mx = fmaxf(mx, L[p]);
        float sum = 0.f;
        #pragma unroll
        for (int p = 0; p < P_SZ; p++) { const float e = __expf(L[p] - mx); L[p] = e; sum += e; }
        const float inv = 1.f / sum;
        #pragma unroll
        for (int p = 0; p < P_SZ; p++) L[p] *= inv;
    }
    __syncthreads();

    // --- sampling: warp = task stride 8, lane = channel
    const int warp = tid >> 5, lane = tid & 31;
    const int LW[3]     = {80, 40, 20};
    const int LSTART[3] = {0, 6400, 8000};

    for (int t = warp; t < QG * H_SZ; t += 8) {
        const int g  = t >> 3, h = t & 7;
        const int bq = b * Q_SZ + q0 + g;
        const float rx = refp[bq * 4 + 0];
        const float ry = refp[bq * 4 + 1];
        const float rw = refp[bq * 4 + 2];
        const float rh = refp[bq * 4 + 3];
        const float* vb = value + ((size_t)(b * H_SZ + h) * S_SZ) * C_SZ + lane;

        float acc = 0.f;
        #pragma unroll
        for (int p = 0; p < P_SZ; p++) {
            const int lvl = p >> 2;
            const int Wl = LW[lvl], Hl = LW[lvl], st = LSTART[lvl];
            const float ox = sh_proj[g][(h * P_SZ + p) * 2 + 0];
            const float oy = sh_proj[g][(h * P_SZ + p) * 2 + 1];
            const float a  = sh_proj[g][192 + h * P_SZ + p];
            // loc = ref + off * (1/4) * ref_wh * 0.5 ; gx = loc*W - 0.5
            const float gx = (rx + ox * rw * 0.125f) * (float)Wl - 0.5f;
            const float gy = (ry + oy * rh * 0.125f) * (float)Hl - 0.5f;
            const float x0f = floorf(gx), y0f = floorf(gy);
            const float wx1 = gx - x0f, wx0 = 1.f - wx1;
            const float wy1 = gy - y0f, wy0 = 1.f - wy1;
            const int x0 = (int)x0f, y0 = (int)y0f;
            const int x1 = x0 + 1,  y1 = y0 + 1;
            const bool xv0 = (x0 >= 0) && (x0 < Wl);
            const bool xv1 = (x1 >= 0) && (x1 < Wl);
            const bool yv0 = (y0 >= 0) && (y0 < Hl);
            const bool yv1 = (y1 >= 0) && (y1 < Hl);
            const float* lv = vb + (size_t)st * C_SZ;
            float s = 0.f;
            if (xv0 && yv0) s += wx0 * wy0 * lv[((size_t)y0 * Wl + x0) * C_SZ];
            if (xv1 && yv0) s += wx1 * wy0 * lv[((size_t)y0 * Wl + x1) * C_SZ];
            if (xv0 && yv1) s += wx0 * wy1 * lv[((size_t)y1 * Wl + x0) * C_SZ];
            if (xv1 && yv1) s += wx1 * wy1 * lv[((size_t)y1 * Wl + x1) * C_SZ];
            acc += a * s;
        }
        mixed[(size_t)bq * D_MODEL + h * C_SZ + lane] = acc;
    }
}

// ---------------------------------------------------------------------------
extern "C" void kernel_launch(void* const* d_in, const int* in_sizes, int n_in,
                              void* d_out, int out_size)
{
    const float* hidden = (const float*)d_in[0];
    const float* enc    = (const float*)d_in[1];
    const float* refp   = (const float*)d_in[2];
    const float* W_off  = (const float*)d_in[3];
    const float* b_off  = (const float*)d_in[4];
    const float* W_attn = (const float*)d_in[5];
    const float* b_attn = (const float*)d_in[6];
    const float* W_val  = (const float*)d_in[7];
    const float* b_val  = (const float*)d_in[8];
    const float* W_out  = (const float*)d_in[9];
    const float* b_out  = (const float*)d_in[10];
    float* out = (float*)d_out;

    float* value = nullptr;
    float* mixed = nullptr;
    cudaGetSymbolAddress((void**)&value, g_value);
    cudaGetSymbolAddress((void**)&mixed, g_mixed);

    // Stage 1: value projection, permuted store to (B,H,S,C)
    {
        const int M = B_SZ * S_SZ;      // 268800
        dim3 grid(256 / 64, M / 64);    // (4, 4200)
        sgemm_k<true><<<grid, 256>>>(enc, W_val, b_val, value, M, 256, S_SZ);
    }

    // Stage 2: fused proj + softmax + sampling
    {
        const int nblk = B_SZ * (Q_SZ / QG);  // 1920
        deform_k<<<nblk, 256>>>(hidden, refp, W_off, b_off, W_attn, b_attn,
                                value, mixed);
    }

    // Stage 3: output projection
    {
        const int M = B_SZ * Q_SZ;      // 9600
        dim3 grid(256 / 64, M / 64);    // (4, 150)
        sgemm_k<false><<<grid, 256>>>(mixed, W_out, b_out, out, M, 256, 1);
    }
}

// round 2
// speedup vs baseline: 1.2782x; 1.2782x over previous
#include <cuda_runtime.h>
#include <cstdint>
#include <cstddef>

// ---------------------------------------------------------------------------
// RT-DETR v2 multiscale deformable attention, fp32.
//   B=32, Q=300, d=256, H=8, C=32, S=8400 (80x80+40x40+20x20), P=12
// Stage 1: value = enc @ W_val + b_val  (stored permuted to (B,H,S,C))
// Stage 2: proj(offs+attn) + softmax + bilinear sampling -> mixed (B,Q,256)
// Stage 3: out = mixed @ W_out + b_out
// Round 2: 128x128x8 double-buffered SGEMM (8x8 microtile) replaces the
//          L1-bound 64x64 version.
// ---------------------------------------------------------------------------

#define B_SZ     32
#define Q_SZ     300
#define D_MODEL  256
#define H_SZ     8
#define C_SZ     32
#define S_SZ     8400
#define P_SZ     12
#define QG       5

__device__ float g_value[(size_t)B_SZ * H_SZ * S_SZ * C_SZ];   // 275 MB
__device__ float g_mixed[(size_t)B_SZ * Q_SZ * D_MODEL];       // 9.8 MB

// ---------------------------------------------------------------------------
// fp32 SGEMM: C[M,N] = A[M,256] * B[256,N] + bias[N]
// 128x128 tile, BK=8, 256 threads, 8x8 per thread, smem double-buffered.
// PERM=true scatters output rows/cols to (B,H,S,C).
// Requires M % 128 == 0, N % 128 == 0, K == 256.
// ---------------------------------------------------------------------------
template <bool PERM>
__global__ __launch_bounds__(256) void sgemm128_k(
    const float* __restrict__ A, const float* __restrict__ Bm,
    const float* __restrict__ bias, float* __restrict__ C,
    int M, int N, int SROWS)
{
    __shared__ float As[2][8][132];   // [buf][k][m] (A transposed in smem)
    __shared__ float Bs[2][8][128];   // [buf][k][n]

    const int tid = threadIdx.x;
    const int m0 = blockIdx.y * 128;
    const int n0 = blockIdx.x * 128;
    const int tx = tid & 15;          // 0..15 -> 2x float4 columns
    const int ty = tid >> 4;          // 0..15 -> 2x float4 rows

    // global loaders
    const int arow = tid >> 1;            // 0..127
    const int acol = (tid & 1) * 4;       // 0 / 4
    const int brow = tid >> 5;            // 0..7
    const int bcol = (tid & 31) * 4;      // 0..124

    const float* Ag = A + (size_t)(m0 + arow) * 256 + acol;
    const float* Bg = Bm + (size_t)brow * N + n0 + bcol;

    float acc[8][8] = {};

    // prime buffer 0
    {
        float4 av = *reinterpret_cast<const float4*>(Ag);
        As[0][acol + 0][arow] = av.x;
        As[0][acol + 1][arow] = av.y;
        As[0][acol + 2][arow] = av.z;
        As[0][acol + 3][arow] = av.w;
        *reinterpret_cast<float4*>(&Bs[0][brow][bcol]) =
            *reinterpret_cast<const float4*>(Bg);
    }
    __syncthreads();

    int buf = 0;
    #pragma unroll 1
    for (int k0 = 8; k0 <= 256; k0 += 8) {
        float4 av2, bv2;
        const bool more = (k0 < 256);
        if (more) {
            av2 = *reinterpret_cast<const float4*>(Ag + k0);
            bv2 = *reinterpret_cast<const float4*>(Bg + (size_t)k0 * N);
        }

        #pragma unroll
        for (int kk = 0; kk < 8; kk++) {
            float a[8], b[8];
            *reinterpret_cast<float4*>(&a[0]) =
                *reinterpret_cast<const float4*>(&As[buf][kk][ty * 4]);
            *reinterpret_cast<float4*>(&a[4]) =
                *reinterpret_cast<const float4*>(&As[buf][kk][64 + ty * 4]);
            *reinterpret_cast<float4*>(&b[0]) =
                *reinterpret_cast<const float4*>(&Bs[buf][kk][tx * 4]);
            *reinterpret_cast<float4*>(&b[4]) =
                *reinterpret_cast<const float4*>(&Bs[buf][kk][64 + tx * 4]);
            #pragma unroll
            for (int i = 0; i < 8; i++)
                #pragma unroll
                for (int j = 0; j < 8; j++)
                    acc[i][j] += a[i] * b[j];
        }

        if (more) {
            buf ^= 1;
            As[buf][acol + 0][arow] = av2.x;
            As[buf][acol + 1][arow] = av2.y;
            As[buf][acol + 2][arow] = av2.z;
            As[buf][acol + 3][arow] = av2.w;
            *reinterpret_cast<float4*>(&Bs[buf][brow][bcol]) = bv2;
            __syncthreads();
        }
    }

    // epilogue: rows {ty*4+i, 64+ty*4+i}, cols {tx*4+j, 64+tx*4+j}
    #pragma unroll
    for (int i = 0; i < 8; i++) {
        const int mr = (i < 4) ? (ty * 4 + i) : (64 + ty * 4 + (i - 4));
        const int m = m0 + mr;
        int bb = 0, ss = 0;
        if (PERM) { bb = m / SROWS; ss = m % SROWS; }
        #pragma unroll
        for (int jg = 0; jg < 2; jg++) {
            const int n = n0 + jg * 64 + tx * 4;
            float4 v;
            v.x = acc[i][jg * 4 + 0] + bias[n + 0];
            v.y = acc[i][jg * 4 + 1] + bias[n + 1];
            v.z = acc[i][jg * 4 + 2] + bias[n + 2];
            v.w = acc[i][jg * 4 + 3] + bias[n + 3];
            if (PERM) {
                const int h = n >> 5, c = n & 31;   // 4 cols stay in one head
                *reinterpret_cast<float4*>(
                    &C[(((size_t)(bb * H_SZ + h)) * SROWS + ss) * C_SZ + c]) = v;
            } else {
                *reinterpret_cast<float4*>(&C[(size_t)m * N + n]) = v;
            }
        }
    }
}

// ---------------------------------------------------------------------------
// Fused: offset/attn projection + softmax + bilinear sampling.
// One block handles QG=5 queries of one batch. 256 threads.
// ---------------------------------------------------------------------------
__global__ __launch_bounds__(256) void deform_k(
    const float* __restrict__ hidden, const float* __restrict__ refp,
    const float* __restrict__ W_off, const float* __restrict__ b_off,
    const float* __restrict__ W_attn, const float* __restrict__ b_attn,
    const float* __restrict__ value, float* __restrict__ mixed)
{
    __shared__ float sh_h[QG][256];
    __shared__ float sh_proj[QG][288];   // [0,192): offsets, [192,288): attn

    const int tid = threadIdx.x;
    const int blk = blockIdx.x;
    const int b   = blk / (Q_SZ / QG);
    const int q0  = (blk % (Q_SZ / QG)) * QG;

    #pragma unroll
    for (int g = 0; g < QG; g++)
        sh_h[g][tid] = hidden[((size_t)(b * Q_SZ + q0 + g)) * 256 + tid];
    __syncthreads();

    for (int j = tid; j < 288; j += 256) {
        const float* col;
        int ncols;
        float bia;
        if (j < 192) { col = W_off + j;          ncols = 192; bia = b_off[j]; }
        else         { col = W_attn + (j - 192); ncols = 96;  bia = b_attn[j - 192]; }
        float s[QG];
        #pragma unroll
        for (int g = 0; g < QG; g++) s[g] = 0.f;
        for (int k = 0; k < 256; k++) {
            const float w = col[(size_t)k * ncols];
            #pragma unroll
            for (int g = 0; g < QG; g++) s[g] += w * sh_h[g][k];
        }
        #pragma unroll
        for (int g = 0; g < QG; g++) sh_proj[g][j] = s[g] + bia;
    }
    __syncthreads();

    if (tid < QG * H_SZ) {
        const int g = tid >> 3, h = tid & 7;
        float* L = &sh_proj[g][192 + h * P_SZ];
        float mx = L[0];
        #pragma unroll
        for (int p = 1; p < P_SZ; p++) mx = fmaxf(mx, L[p]);
        float sum = 0.f;
        #pragma unroll
        for (int p = 0; p < P_SZ; p++) { const float e = __expf(L[p] - mx); L[p] = e; sum += e; }
        const float inv = 1.f / sum;
        #pragma unroll
        for (int p = 0; p < P_SZ; p++) L[p] *= inv;
    }
    __syncthreads();

    const int warp = tid >> 5, lane = tid & 31;
    const int LW[3]     = {80, 40, 20};
    const int LSTART[3] = {0, 6400, 8000};

    for (int t = warp; t < QG * H_SZ; t += 8) {
        const int g  = t >> 3, h = t & 7;
        const int bq = b * Q_SZ + q0 + g;
        const float rx = refp[bq * 4 + 0];
        const float ry = refp[bq * 4 + 1];
        const float rw = refp[bq * 4 + 2];
        const float rh = refp[bq * 4 + 3];
        const float* vb = value + ((size_t)(b * H_SZ + h) * S_SZ) * C_SZ + lane;

        float acc = 0.f;
        #pragma unroll
        for (int p = 0; p < P_SZ; p++) {
            const int lvl = p >> 2;
            const int Wl = LW[lvl], Hl = LW[lvl], st = LSTART[lvl];
            const float ox = sh_proj[g][(h * P_SZ + p) * 2 + 0];
            const float oy = sh_proj[g][(h * P_SZ + p) * 2 + 1];
            const float a  = sh_proj[g][192 + h * P_SZ + p];
            const float gx = (rx + ox * rw * 0.125f) * (float)Wl - 0.5f;
            const float gy = (ry + oy * rh * 0.125f) * (float)Hl - 0.5f;
            const float x0f = floorf(gx), y0f = floorf(gy);
            const float wx1 = gx - x0f, wx0 = 1.f - wx1;
            const float wy1 = gy - y0f, wy0 = 1.f - wy1;
            const int x0 = (int)x0f, y0 = (int)y0f;
            const int x1 = x0 + 1,  y1 = y0 + 1;
            const bool xv0 = (x0 >= 0) && (x0 < Wl);
            const bool xv1 = (x1 >= 0) && (x1 < Wl);
            const bool yv0 = (y0 >= 0) && (y0 < Hl);
            const bool yv1 = (y1 >= 0) && (y1 < Hl);
            const float* lv = vb + (size_t)st * C_SZ;
            float s = 0.f;
            if (xv0 && yv0) s += wx0 * wy0 * lv[((size_t)y0 * Wl + x0) * C_SZ];
            if (xv1 && yv0) s += wx1 * wy0 * lv[((size_t)y0 * Wl + x1) * C_SZ];
            if (xv0 && yv1) s += wx0 * wy1 * lv[((size_t)y1 * Wl + x0) * C_SZ];
            if (xv1 && yv1) s += wx1 * wy1 * lv[((size_t)y1 * Wl + x1) * C_SZ];
            acc += a * s;
        }
        mixed[(size_t)bq * D_MODEL + h * C_SZ + lane] = acc;
    }
}

// ---------------------------------------------------------------------------
extern "C" void kernel_launch(void* const* d_in, const int* in_sizes, int n_in,
                              void* d_out, int out_size)
{
    const float* hidden = (const float*)d_in[0];
    const float* enc    = (const float*)d_in[1];
    const float* refp   = (const float*)d_in[2];
    const float* W_off  = (const float*)d_in[3];
    const float* b_off  = (const float*)d_in[4];
    const float* W_attn = (const float*)d_in[5];
    const float* b_attn = (const float*)d_in[6];
    const float* W_val  = (const float*)d_in[7];
    const float* b_val  = (const float*)d_in[8];
    const float* W_out  = (const float*)d_in[9];
    const float* b_out  = (const float*)d_in[10];
    float* out = (float*)d_out;

    float* value = nullptr;
    float* mixed = nullptr;
    cudaGetSymbolAddress((void**)&value, g_value);
    cudaGetSymbolAddress((void**)&mixed, g_mixed);

    // Stage 1: value projection, permuted store to (B,H,S,C)
    {
        const int M = B_SZ * S_SZ;        // 268800 = 2100 * 128
        dim3 grid(256 / 128, M / 128);    // (2, 2100)
        sgemm128_k<true><<<grid, 256>>>(enc, W_val, b_val, value, M, 256, S_SZ);
    }

    // Stage 2: fused proj + softmax + sampling
    {
        const int nblk = B_SZ * (Q_SZ / QG);  // 1920
        deform_k<<<nblk, 256>>>(hidden, refp, W_off, b_off, W_attn, b_attn,
                                value, mixed);
    }

    // Stage 3: output projection
    {
        const int M = B_SZ * Q_SZ;        // 9600 = 75 * 128
        dim3 grid(256 / 128, M / 128);    // (2, 75)
        sgemm128_k<false><<<grid, 256>>>(mixed, W_out, b_out, out, M, 256, 1);
    }
}

// round 4
// speedup vs baseline: 1.7435x; 1.3640x over previous
#include <cuda_runtime.h>
#include <cuda_bf16.h>
#include <cstdint>
#include <cstddef>

// ---------------------------------------------------------------------------
// RT-DETR v2 multiscale deformable attention.
//   B=32, Q=300, d=256, H=8, C=32, S=8400, P=12
// Stage 0: W_val -> transposed bf16 hi/lo split (tiny prep kernel)
// Stage 1: value = enc @ W_val + b_val via warp-level HMMA bf16 3-split,
//          output permuted to (B,H,S,C)
// Stage 2: proj(offs+attn) + softmax + bilinear sampling -> mixed
// Stage 3: out = mixed @ W_out + b_out (fp32 SGEMM)
// ---------------------------------------------------------------------------

#define B_SZ     32
#define Q_SZ     300
#define D_MODEL  256
#define H_SZ     8
#define C_SZ     32
#define S_SZ     8400
#define P_SZ     12
#define QG       5

__device__ float g_value[(size_t)B_SZ * H_SZ * S_SZ * C_SZ];   // 275 MB
__device__ float g_mixed[(size_t)B_SZ * Q_SZ * D_MODEL];       // 9.8 MB
__device__ __nv_bfloat16 g_whi[256 * 256];                      // W_val^T hi
__device__ __nv_bfloat16 g_wlo[256 * 256];                      // W_val^T lo

// ======================= Stage 0: weight prep ==============================
// W [K=256][N=256] fp32 -> W^T [N][K] bf16 hi/lo
__global__ void wprep_k(const float* __restrict__ W,
                        __nv_bfloat16* __restrict__ whi,
                        __nv_bfloat16* __restrict__ wlo)
{
    const int n = blockIdx.x;      // 256
    const int k = threadIdx.x;     // 256
    const float v = W[(size_t)k * 256 + n];
    const __nv_bfloat16 h = __float2bfloat16_rn(v);
    const float lo = v - __bfloat162float(h);
    whi[(size_t)n * 256 + k] = h;
    wlo[(size_t)n * 256 + k] = __float2bfloat16_rn(lo);
}

// ======================= Stage 1: HMMA bf16 GEMM ===========================
__device__ __forceinline__ uint32_t pkbf(float x, float y) {
    __nv_bfloat162 t = __floats2bfloat162_rn(x, y);
    return *reinterpret_cast<uint32_t*>(&t);
}

__device__ __forceinline__ void mma16816(float* d, const uint32_t* a,
                                         const uint32_t* b) {
    asm volatile(
        "mma.sync.aligned.m16n8k16.row.col.f32.bf16.bf16.f32 "
        "{%0,%1,%2,%3}, {%4,%5,%6,%7}, {%8,%9}, {%0,%1,%2,%3};"
        : "+f"(d[0]), "+f"(d[1]), "+f"(d[2]), "+f"(d[3])
        : "r"(a[0]), "r"(a[1]), "r"(a[2]), "r"(a[3]), "r"(b[0]), "r"(b[1]));
}

#define PITCH 18   // bf16 elems per smem row (16 data + 2 pad, avoids conflicts)

// C[M,256] = A[M,256] * W^T + bias, stored permuted to (B,H,S,C).
// 128x128 tile, 256 threads (8 warps of 32x64), K-chunks of 16, double-buffered.
__global__ __launch_bounds__(256) void gemm_hmma_k(
    const float* __restrict__ A,
    const __nv_bfloat16* __restrict__ Whi,
    const __nv_bfloat16* __restrict__ Wlo,
    const float* __restrict__ bias,
    float* __restrict__ C)
{
    __shared__ uint16_t sA[2][2][128 * PITCH];   // [buf][hi/lo][row*PITCH+k]
    __shared__ uint16_t sB[2][2][128 * PITCH];

    const int tid  = threadIdx.x;
    const int wid  = tid >> 5;
    const int lane = tid & 31;
    const int m0 = blockIdx.y * 128;
    const int n0 = blockIdx.x * 128;

    const int wm = wid & 3;            // 4 M-groups of 32
    const int wn = wid >> 2;           // 2 N-groups of 64
    const int m0w = wm * 32;
    const int n0w = wn * 64;

    // global loader geometry
    const int arow0 = tid >> 2;                // A: f4 index i -> row i>>2
    const int ac0   = (tid & 3) * 4;           //    col (i&3)*4
    const int arow1 = (tid + 256) >> 2;
    const int ac1   = ((tid + 256) & 3) * 4;
    const int brow  = tid >> 1;                // B: row t>>1
    const int boff  = (tid & 1) * 8;           //    bf16 col offset

    float acc[2][8][4] = {};

    float4 pa0, pa1;
    uint4  pbh, pbl;

    // --- prefetch + store chunk 0
    {
        pa0 = *reinterpret_cast<const float4*>(&A[(size_t)(m0 + arow0) * 256 + ac0]);
        pa1 = *reinterpret_cast<const float4*>(&A[(size_t)(m0 + arow1) * 256 + ac1]);
        pbh = *reinterpret_cast<const uint4*>(&Whi[(size_t)(n0 + brow) * 256 + boff]);
        pbl = *reinterpret_cast<const uint4*>(&Wlo[(size_t)(n0 + brow) * 256 + boff]);
    }
    #define STORE_CHUNK(BUF) do {                                              \
        /* A row 0 */                                                          \
        {   const float x0 = pa0.x, x1 = pa0.y, x2 = pa0.z, x3 = pa0.w;        \
            const float h0 = __bfloat162float(__float2bfloat16_rn(x0));        \
            const float h1 = __bfloat162float(__float2bfloat16_rn(x1));        \
            const float h2 = __bfloat162float(__float2bfloat16_rn(x2));        \
            const float h3 = __bfloat162float(__float2bfloat16_rn(x3));        \
            uint16_t* p = &sA[BUF][0][arow0 * PITCH + ac0];                    \
            *reinterpret_cast<uint32_t*>(p)     = pkbf(h0, h1);                \
            *reinterpret_cast<uint32_t*>(p + 2) = pkbf(h2, h3);                \
            uint16_t* q = &sA[BUF][1][arow0 * PITCH + ac0];                    \
            *reinterpret_cast<uint32_t*>(q)     = pkbf(x0 - h0, x1 - h1);      \
            *reinterpret_cast<uint32_t*>(q + 2) = pkbf(x2 - h2, x3 - h3);      \
        }                                                                      \
        /* A row 1 */                                                          \
        {   const float x0 = pa1.x, x1 = pa1.y, x2 = pa1.z, x3 = pa1.w;        \
            const float h0 = __bfloat162float(__float2bfloat16_rn(x0));        \
            const float h1 = __bfloat162float(__float2bfloat16_rn(x1));        \
            const float h2 = __bfloat162float(__float2bfloat16_rn(x2));        \
            const float h3 = __bfloat162float(__float2bfloat16_rn(x3));        \
            uint16_t* p = &sA[BUF][0][arow1 * PITCH + ac1];                    \
            *reinterpret_cast<uint32_t*>(p)     = pkbf(h0, h1);                \
            *reinterpret_cast<uint32_t*>(p + 2) = pkbf(h2, h3);                \
            uint16_t* q = &sA[BUF][1][arow1 * PITCH + ac1];                    \
            *reinterpret_cast<uint32_t*>(q)     = pkbf(x0 - h0, x1 - h1);      \
            *reinterpret_cast<uint32_t*>(q + 2) = pkbf(x2 - h2, x3 - h3);      \
        }                                                                      \
        /* B */                                                                \
        {   uint16_t* p = &sB[BUF][0][brow * PITCH + boff];                    \
            *reinterpret_cast<uint32_t*>(p)     = pbh.x;                       \
            *reinterpret_cast<uint32_t*>(p + 2) = pbh.y;                       \
            *reinterpret_cast<uint32_t*>(p + 4) = pbh.z;                       \
            *reinterpret_cast<uint32_t*>(p + 6) = pbh.w;                       \
            uint16_t* q = &sB[BUF][1][brow * PITCH + boff];                    \
            *reinterpret_cast<uint32_t*>(q)     = pbl.x;                       \
            *reinterpret_cast<uint32_t*>(q + 2) = pbl.y;                       \
            *reinterpret_cast<uint32_t*>(q + 4) = pbl.z;                       \
            *reinterpret_cast<uint32_t*>(q + 6) = pbl.w;                       \
        }                                                                      \
    } while (0)

    STORE_CHUNK(0);
    __syncthreads();

    const int lr = lane >> 2;           // 0..7
    const int lc2 = (lane & 3) * 2;     // 0,2,4,6

    #pragma unroll 1
    for (int c = 0; c < 16; ++c) {
        const int buf = c & 1;
        if (c < 15) {
            const int k0 = (c + 1) * 16;
            pa0 = *reinterpret_cast<const float4*>(&A[(size_t)(m0 + arow0) * 256 + k0 + ac0]);
            pa1 = *reinterpret_cast<const float4*>(&A[(size_t)(m0 + arow1) * 256 + k0 + ac1]);
            pbh = *reinterpret_cast<const uint4*>(&Whi[(size_t)(n0 + brow) * 256 + k0 + boff]);
            pbl = *reinterpret_cast<const uint4*>(&Wlo[(size_t)(n0 + brow) * 256 + k0 + boff]);
        }

        // load fragments
        uint32_t ah[2][4], al[2][4], bh[8][2], bl[8][2];
        #pragma unroll
        for (int mt = 0; mt < 2; mt++) {
            const int r = m0w + mt * 16 + lr;
            ah[mt][0] = *reinterpret_cast<const uint32_t*>(&sA[buf][0][r * PITCH + lc2]);
            ah[mt][1] = *reinterpret_cast<const uint32_t*>(&sA[buf][0][(r + 8) * PITCH + lc2]);
            ah[mt][2] = *reinterpret_cast<const uint32_t*>(&sA[buf][0][r * PITCH + lc2 + 8]);
            ah[mt][3] = *reinterpret_cast<const uint32_t*>(&sA[buf][0][(r + 8) * PITCH + lc2 + 8]);
            al[mt][0] = *reinterpret_cast<const uint32_t*>(&sA[buf][1][r * PITCH + lc2]);
            al[mt][1] = *reinterpret_cast<const uint32_t*>(&sA[buf][1][(r + 8) * PITCH + lc2]);
            al[mt][2] = *reinterpret_cast<const uint32_t*>(&sA[buf][1][r * PITCH + lc2 + 8]);
            al[mt][3] = *reinterpret_cast<const uint32_t*>(&sA[buf][1][(r + 8) * PITCH + lc2 + 8]);
        }
        #pragma unroll
        for (int nt = 0; nt < 8; nt++) {
            const int r = n0w + nt * 8 + lr;
            bh[nt][0] = *reinterpret_cast<const uint32_t*>(&sB[buf][0][r * PITCH + lc2]);
            bh[nt][1] = *reinterpret_cast<const uint32_t*>(&sB[buf][0][r * PITCH + lc2 + 8]);
            bl[nt][0] = *reinterpret_cast<const uint32_t*>(&sB[buf][1][r * PITCH + lc2]);
            bl[nt][1] = *reinterpret_cast<const uint32_t*>(&sB[buf][1][r * PITCH + lc2 + 8]);
        }

        #pragma unroll
        for (int mt = 0; mt < 2; mt++)
            #pragma unroll
            for (int nt = 0; nt < 8; nt++) {
                mma16816(acc[mt][nt], ah[mt], bh[nt]);
                mma16816(acc[mt][nt], al[mt], bh[nt]);
                mma16816(acc[mt][nt], ah[mt], bl[nt]);
            }

        if (c < 15) {
            STORE_CHUNK(buf ^ 1);
            __syncthreads();
        }
    }

    // --- epilogue: permuted store (B,H,S,C) with bias
    #pragma unroll
    for (int mt = 0; mt < 2; mt++) {
        const int mA = m0 + m0w + mt * 16 + lr;
        const int mB = mA + 8;
        const int bbA = mA / S_SZ, ssA = mA % S_SZ;
        const int bbB = mB / S_SZ, ssB = mB % S_SZ;
        #pragma unroll
        for (int nt = 0; nt < 8; nt++) {
            const int n = n0 + n0w + nt * 8 + lc2;
            const int h = n >> 5, cc = n & 31;
            const float bi0 = bias[n], bi1 = bias[n + 1];
            float2 v0, v1;
            v0.x = acc[mt][nt][0] + bi0;
            v0.y = acc[mt][nt][1] + bi1;
            v1.x = acc[mt][nt][2] + bi0;
            v1.y = acc[mt][nt][3] + bi1;
            *reinterpret_cast<float2*>(
                &C[(((size_t)(bbA * H_SZ + h)) * S_SZ + ssA) * C_SZ + cc]) = v0;
            *reinterpret_cast<float2*>(
                &C[(((size_t)(bbB * H_SZ + h)) * S_SZ + ssB) * C_SZ + cc]) = v1;
        }
    }
}

// ======================= Stage 3: fp32 SGEMM ===============================
__global__ __launch_bounds__(256) void sgemm128_k(
    const float* __restrict__ A, const float* __restrict__ Bm,
    const float* __restrict__ bias, float* __restrict__ C, int N)
{
    __shared__ float As[2][8][132];
    __shared__ float Bs[2][8][128];

    const int tid = threadIdx.x;
    const int m0 = blockIdx.y * 128;
    const int n0 = blockIdx.x * 128;
    const int tx = tid & 15;
    const int ty = tid >> 4;

    const int arow = tid >> 1;
    const int acol = (tid & 1) * 4;
    const int brow = tid >> 5;
    const int bcol = (tid & 31) * 4;

    const float* Ag = A + (size_t)(m0 + arow) * 256 + acol;
    const float* Bg = Bm + (size_t)brow * N + n0 + bcol;

    float acc[8][8] = {};

    {
        float4 av = *reinterpret_cast<const float4*>(Ag);
        As[0][acol + 0][arow] = av.x;
        As[0][acol + 1][arow] = av.y;
        As[0][acol + 2][arow] = av.z;
        As[0][acol + 3][arow] = av.w;
        *reinterpret_cast<float4*>(&Bs[0][brow][bcol]) =
            *reinterpret_cast<const float4*>(Bg);
    }
    __syncthreads();

    int buf = 0;
    #pragma unroll 1
    for (int k0 = 8; k0 <= 256; k0 += 8) {
        float4 av2, bv2;
        const bool more = (k0 < 256);
        if (more) {
            av2 = *reinterpret_cast<const float4*>(Ag + k0);
            bv2 = *reinterpret_cast<const float4*>(Bg + (size_t)k0 * N);
        }
        #pragma unroll
        for (int kk = 0; kk < 8; kk++) {
            float a[8], b[8];
            *reinterpret_cast<float4*>(&a[0]) =
                *reinterpret_cast<const float4*>(&As[buf][kk][ty * 4]);
            *reinterpret_cast<float4*>(&a[4]) =
                *reinterpret_cast<const float4*>(&As[buf][kk][64 + ty * 4]);
            *reinterpret_cast<float4*>(&b[0]) =
                *reinterpret_cast<const float4*>(&Bs[buf][kk][tx * 4]);
            *reinterpret_cast<float4*>(&b[4]) =
                *reinterpret_cast<const float4*>(&Bs[buf][kk][64 + tx * 4]);
            #pragma unroll
            for (int i = 0; i < 8; i++)
                #pragma unroll
                for (int j = 0; j < 8; j++)
                    acc[i][j] += a[i] * b[j];
        }
        if (more) {
            buf ^= 1;
            As[buf][acol + 0][arow] = av2.x;
            As[buf][acol + 1][arow] = av2.y;
            As[buf][acol + 2][arow] = av2.z;
            As[buf][acol + 3][arow] = av2.w;
            *reinterpret_cast<float4*>(&Bs[buf][brow][bcol]) = bv2;
            __syncthreads();
        }
    }

    #pragma unroll
    for (int i = 0; i < 8; i++) {
        const int mr = (i < 4) ? (ty * 4 + i) : (64 + ty * 4 + (i - 4));
        const int m = m0 + mr;
        #pragma unroll
        for (int jg = 0; jg < 2; jg++) {
            const int n = n0 + jg * 64 + tx * 4;
            float4 v;
            v.x = acc[i][jg * 4 + 0] + bias[n + 0];
            v.y = acc[i][jg * 4 + 1] + bias[n + 1];
            v.z = acc[i][jg * 4 + 2] + bias[n + 2];
            v.w = acc[i][jg * 4 + 3] + bias[n + 3];
            *reinterpret_cast<float4*>(&C[(size_t)m * N + n]) = v;
        }
    }
}

// ======================= Stage 2: fused deform =============================
__global__ __launch_bounds__(256) void deform_k(
    const float* __restrict__ hidden, const float* __restrict__ refp,
    const float* __restrict__ W_off, const float* __restrict__ b_off,
    const float* __restrict__ W_attn, const float* __restrict__ b_attn,
    const float* __restrict__ value, float* __restrict__ mixed)
{
    __shared__ float sh_h[QG][256];
    __shared__ float sh_proj[QG][288];

    const int tid = threadIdx.x;
    const int blk = blockIdx.x;
    const int b   = blk / (Q_SZ / QG);
    const int q0  = (blk % (Q_SZ / QG)) * QG;

    #pragma unroll
    for (int g = 0; g < QG; g++)
        sh_h[g][tid] = hidden[((size_t)(b * Q_SZ + q0 + g)) * 256 + tid];
    __syncthreads();

    for (int j = tid; j < 288; j += 256) {
        const float* col;
        int ncols;
        float bia;
        if (j < 192) { col = W_off + j;          ncols = 192; bia = b_off[j]; }
        else         { col = W_attn + (j - 192); ncols = 96;  bia = b_attn[j - 192]; }
        float s[QG];
        #pragma unroll
        for (int g = 0; g < QG; g++) s[g] = 0.f;
        for (int k = 0; k < 256; k++) {
            const float w = col[(size_t)k * ncols];
            #pragma unroll
            for (int g = 0; g < QG; g++) s[g] += w * sh_h[g][k];
        }
        #pragma unroll
        for (int g = 0; g < QG; g++) sh_proj[g][j] = s[g] + bia;
    }
    __syncthreads();

    if (tid < QG * H_SZ) {
        const int g = tid >> 3, h = tid & 7;
        float* L = &sh_proj[g][192 + h * P_SZ];
        float mx = L[0];
        #pragma unroll
        for (int p = 1; p < P_SZ; p++) mx = fmaxf(mx, L[p]);
        float sum = 0.f;
        #pragma unroll
        for (int p = 0; p < P_SZ; p++) { const float e = __expf(L[p] - mx); L[p] = e; sum += e; }
        const float inv = 1.f / sum;
        #pragma unroll
        for (int p = 0; p < P_SZ; p++) L[p] *= inv;
    }
    __syncthreads();

    const int warp = tid >> 5, lane = tid & 31;
    const int LW[3]     = {80, 40, 20};
    const int LSTART[3] = {0, 6400, 8000};

    for (int t = warp; t < QG * H_SZ; t += 8) {
        const int g  = t >> 3, h = t & 7;
        const int bq = b * Q_SZ + q0 + g;
        const float rx = refp[bq * 4 + 0];
        const float ry = refp[bq * 4 + 1];
        const float rw = refp[bq * 4 + 2];
        const float rh = refp[bq * 4 + 3];
        const float* vb = value + ((size_t)(b * H_SZ + h) * S_SZ) * C_SZ + lane;

        float acc = 0.f;
        #pragma unroll
        for (int p = 0; p < P_SZ; p++) {
            const int lvl = p >> 2;
            const int Wl = LW[lvl], Hl = LW[lvl], st = LSTART[lvl];
            const float ox = sh_proj[g][(h * P_SZ + p) * 2 + 0];
            const float oy = sh_proj[g][(h * P_SZ + p) * 2 + 1];
            const float a  = sh_proj[g][192 + h * P_SZ + p];
            const float gx = (rx + ox * rw * 0.125f) * (float)Wl - 0.5f;
            const float gy = (ry + oy * rh * 0.125f) * (float)Hl - 0.5f;
            const float x0f = floorf(gx), y0f = floorf(gy);
            const float wx1 = gx - x0f, wx0 = 1.f - wx1;
            const float wy1 = gy - y0f, wy0 = 1.f - wy1;
            const int x0 = (int)x0f, y0 = (int)y0f;
            const int x1 = x0 + 1,  y1 = y0 + 1;
            const bool xv0 = (x0 >= 0) && (x0 < Wl);
            const bool xv1 = (x1 >= 0) && (x1 < Wl);
            const bool yv0 = (y0 >= 0) && (y0 < Hl);
            const bool yv1 = (y1 >= 0) && (y1 < Hl);
            const float* lv = vb + (size_t)st * C_SZ;
            float s = 0.f;
            if (xv0 && yv0) s += wx0 * wy0 * lv[((size_t)y0 * Wl + x0) * C_SZ];
            if (xv1 && yv0) s += wx1 * wy0 * lv[((size_t)y0 * Wl + x1) * C_SZ];
            if (xv0 && yv1) s += wx0 * wy1 * lv[((size_t)y1 * Wl + x0) * C_SZ];
            if (xv1 && yv1) s += wx1 * wy1 * lv[((size_t)y1 * Wl + x1) * C_SZ];
            acc += a * s;
        }
        mixed[(size_t)bq * D_MODEL + h * C_SZ + lane] = acc;
    }
}

// ---------------------------------------------------------------------------
extern "C" void kernel_launch(void* const* d_in, const int* in_sizes, int n_in,
                              void* d_out, int out_size)
{
    const float* hidden = (const float*)d_in[0];
    const float* enc    = (const float*)d_in[1];
    const float* refp   = (const float*)d_in[2];
    const float* W_off  = (const float*)d_in[3];
    const float* b_off  = (const float*)d_in[4];
    const float* W_attn = (const float*)d_in[5];
    const float* b_attn = (const float*)d_in[6];
    const float* W_val  = (const float*)d_in[7];
    const float* b_val  = (const float*)d_in[8];
    const float* W_out  = (const float*)d_in[9];
    const float* b_out  = (const float*)d_in[10];
    float* out = (float*)d_out;

    float* value = nullptr;
    float* mixed = nullptr;
    __nv_bfloat16* whi = nullptr;
    __nv_bfloat16* wlo = nullptr;
    cudaGetSymbolAddress((void**)&value, g_value);
    cudaGetSymbolAddress((void**)&mixed, g_mixed);
    cudaGetSymbolAddress((void**)&whi, g_whi);
    cudaGetSymbolAddress((void**)&wlo, g_wlo);

    // Stage 0: weight transpose + hi/lo split
    wprep_k<<<256, 256>>>(W_val, whi, wlo);

    // Stage 1: value projection (HMMA bf16 3-split), permuted store
    {
        const int M = B_SZ * S_SZ;      // 268800 = 2100 * 128
        dim3 grid(2, M / 128);
        gemm_hmma_k<<<grid, 256>>>(enc, whi, wlo, b_val, value);
    }

    // Stage 2: fused proj + softmax + sampling
    {
        const int nblk = B_SZ * (Q_SZ / QG);
        deform_k<<<nblk, 256>>>(hidden, refp, W_off, b_off, W_attn, b_attn,
                                value, mixed);
    }

    // Stage 3: output projection (fp32)
    {
        const int M = B_SZ * Q_SZ;      // 9600 = 75 * 128
        dim3 grid(2, M / 128);
        sgemm128_k<<<grid, 256>>>(mixed, W_out, b_out, out, 256);
    }
}